// round 2
// baseline (speedup 1.0000x reference)
#include <cuda_runtime.h>

// MultiLevelAlignedRoIPooling
// feat2: (2,256,256,256) f32   feat3: (2,128,128,256)
// feat4: (2, 64, 64,256)       feat5: (2, 32, 32,256)
// boxes: (2,512,4)  -> out: (2,512,7,7,256) f32

#define PP 7
#define CC 256
#define NB 512
#define BB 2

__global__ __launch_bounds__(256)
void roi_align_kernel(const float* __restrict__ f2,
                      const float* __restrict__ f3,
                      const float* __restrict__ f4,
                      const float* __restrict__ f5,
                      const float* __restrict__ boxes,
                      float* __restrict__ out)
{
    // block = one (b, n, py)
    int blk = blockIdx.x;
    int py  = blk % PP;
    int bn  = blk / PP;          // b*NB + n
    int b   = bn / NB;

    // ---- box scalars (redundant per-thread, cheap) ----
    const float4 bx4 = __ldg(&((const float4*)boxes)[bn]);
    float y1 = bx4.x, x1 = bx4.y, y2 = bx4.z, x2 = bx4.w;
    float bh = y2 - y1, bw = x2 - x1;
    float area_sqrt = sqrtf(bh * bw);
    int lv = (int)floorf(logf(area_sqrt / 224.0f) / logf(2.0f)) + 4;
    lv = min(max(lv, 2), 5);
    int li = lv - 2;
    float inv_scale = exp2f(-(float)lv);

    float ry1 = y1 * inv_scale - 0.5f;
    float rx1 = x1 * inv_scale - 0.5f;
    float ry2 = y2 * inv_scale - 0.5f;
    float rx2 = x2 * inv_scale - 0.5f;
    float rh = ry2 - ry1, rw = rx2 - rx1;

    int Hl = 256 >> li;
    float bnd = (float)Hl - 1.0f;

    // vertical sample for this py
    float gy  = fminf(ry1 + (float)py * (rh / (float)PP), bnd);
    float y0f = floorf(gy);
    float ly  = gy - y0f;
    float hy  = 1.0f - ly;
    int   y0  = (int)y0f;
    int   y1i = min(y0 + 1, Hl - 1);    // clamped case carries weight ly==0

    const float* f = (li == 0) ? f2 : (li == 1) ? f3 : (li == 2) ? f4 : f5;
    const float* fb = f + (size_t)b * Hl * Hl * CC;
    const float4* __restrict__ row0 = (const float4*)(fb + (size_t)y0  * Hl * CC);
    const float4* __restrict__ row1 = (const float4*)(fb + (size_t)y1i * Hl * CC);

    float* __restrict__ outp = out + (((size_t)bn * PP + py) * PP) * CC;

    int t   = threadIdx.x;
    int c4  = t & 63;        // float4 index within channel dim (256/4 = 64)
    int px0 = t >> 6;        // 0..3

    float rwp = rw / (float)PP;

    // ---- horizontal params for both px positions this thread covers ----
    int pxA = px0;                    // 0..3, always stored
    int pxB = px0 + 4;                // 4..7; 7 is invalid -> clamp, no store
    bool storeB = (pxB < PP);
    int pxBc = storeB ? pxB : 6;

    float gxA  = fminf(rx1 + (float)pxA  * rwp, bnd);
    float gxB  = fminf(rx1 + (float)pxBc * rwp, bnd);
    float xA0f = floorf(gxA), xB0f = floorf(gxB);
    float lxA = gxA - xA0f, lxB = gxB - xB0f;
    float hxA = 1.0f - lxA, hxB = 1.0f - lxB;
    int xA0 = (int)xA0f,          xB0 = (int)xB0f;
    int xA1 = min(xA0 + 1, Hl-1), xB1 = min(xB0 + 1, Hl-1);

    // ---- issue all 8 loads up front (MLP=8) ----
    const float4 a00 = __ldg(&row0[(size_t)xA0 * 64 + c4]);
    const float4 a01 = __ldg(&row0[(size_t)xA1 * 64 + c4]);
    const float4 a10 = __ldg(&row1[(size_t)xA0 * 64 + c4]);
    const float4 a11 = __ldg(&row1[(size_t)xA1 * 64 + c4]);
    const float4 b00 = __ldg(&row0[(size_t)xB0 * 64 + c4]);
    const float4 b01 = __ldg(&row0[(size_t)xB1 * 64 + c4]);
    const float4 b10 = __ldg(&row1[(size_t)xB0 * 64 + c4]);
    const float4 b11 = __ldg(&row1[(size_t)xB1 * 64 + c4]);

    // ---- blend A ----
    {
        float w00 = hy * hxA, w01 = hy * lxA, w10 = ly * hxA, w11 = ly * lxA;
        float4 r;
        r.x = w00*a00.x + w01*a01.x + w10*a10.x + w11*a11.x;
        r.y = w00*a00.y + w01*a01.y + w10*a10.y + w11*a11.y;
        r.z = w00*a00.z + w01*a01.z + w10*a10.z + w11*a11.z;
        r.w = w00*a00.w + w01*a01.w + w10*a10.w + w11*a11.w;
        __stcs((float4*)(outp + ((size_t)pxA * 64 + c4) * 4), r);
    }

    // ---- blend B ----
    if (storeB) {
        float w00 = hy * hxB, w01 = hy * lxB, w10 = ly * hxB, w11 = ly * lxB;
        float4 r;
        r.x = w00*b00.x + w01*b01.x + w10*b10.x + w11*b11.x;
        r.y = w00*b00.y + w01*b01.y + w10*b10.y + w11*b11.y;
        r.z = w00*b00.z + w01*b01.z + w10*b10.z + w11*b11.z;
        r.w = w00*b00.w + w01*b01.w + w10*b10.w + w11*b11.w;
        __stcs((float4*)(outp + ((size_t)pxB * 64 + c4) * 4), r);
    }
}

extern "C" void kernel_launch(void* const* d_in, const int* in_sizes, int n_in,
                              void* d_out, int out_size)
{
    const float* f2    = (const float*)d_in[0];
    const float* f3    = (const float*)d_in[1];
    const float* f4    = (const float*)d_in[2];
    const float* f5    = (const float*)d_in[3];
    const float* boxes = (const float*)d_in[4];
    float* out = (float*)d_out;

    dim3 grid(BB * NB * PP);   // 7168 blocks, one per (b,n,py)
    dim3 block(256);
    roi_align_kernel<<<grid, block>>>(f2, f3, f4, f5, boxes, out);
}